// round 12
// baseline (speedup 1.0000x reference)
#include <cuda_runtime.h>
#include <math.h>

static const int T  = 2048;
static const int C  = 1024;
static const int NH = 16;
static const int HS = 64;
#define EPS_GN 0.00064f

typedef unsigned long long u64;
typedef unsigned int u32;

// ---------------- f32x2 packed helpers ----------------
__device__ __forceinline__ u64 fma2(u64 a, u64 b, u64 c) {
    u64 d; asm("fma.rn.f32x2 %0, %1, %2, %3;" : "=l"(d) : "l"(a), "l"(b), "l"(c)); return d;
}
__device__ __forceinline__ u64 mul2(u64 a, u64 b) {
    u64 d; asm("mul.rn.f32x2 %0, %1, %2;" : "=l"(d) : "l"(a), "l"(b)); return d;
}
__device__ __forceinline__ u64 add2(u64 a, u64 b) {
    u64 d; asm("add.rn.f32x2 %0, %1, %2;" : "=l"(d) : "l"(a), "l"(b)); return d;
}
__device__ __forceinline__ u64 pack2(float lo, float hi) {
    u64 d; asm("mov.b64 %0, {%1, %2};" : "=l"(d) : "f"(lo), "f"(hi)); return d;
}
__device__ __forceinline__ float2 unpack2(u64 v) {
    float2 r; asm("mov.b64 {%0, %1}, %2;" : "=f"(r.x), "=f"(r.y) : "l"(v)); return r;
}
__device__ __forceinline__ void cp16(unsigned s, const float* g) {
    asm volatile("cp.async.ca.shared.global [%0], [%1], 16;" :: "r"(s), "l"(g));
}

// ---------------- scratch ----------------
__device__ float g_scratch[(size_t)17 * 2048 * 1024 + (size_t)2048 * 288];

// ---------------- K1: token shift + 6-way mix ----------------
__global__ void k_shift_mix(const float* __restrict__ x, const float* __restrict__ x_prev,
                            const int* __restrict__ cu, int ncu,
                            const float* __restrict__ mr, const float* __restrict__ mw,
                            const float* __restrict__ mk, const float* __restrict__ mv,
                            const float* __restrict__ ma, const float* __restrict__ mg,
                            float* __restrict__ oxr, float* __restrict__ oxw,
                            float* __restrict__ oxk, float* __restrict__ oxv,
                            float* __restrict__ oxa, float* __restrict__ oxg) {
    const int t = blockIdx.x;
    int kind = (t == 0) ? 1 : 0;
    int prow = 0;
    for (int i = 0; i + 1 < ncu; i++) if (cu[i] == t) { kind = 2; prow = i; }
    const int c = threadIdx.x * 4;
    const size_t off = (size_t)t * C + c;
    float4 xc = *(const float4*)(x + off);
    float4 pv;
    if (kind == 0)      pv = *(const float4*)(x + off - C);
    else if (kind == 2) pv = *(const float4*)(x_prev + (size_t)prow * C + c);
    else                pv = make_float4(0.f, 0.f, 0.f, 0.f);
    float4 dx = make_float4(pv.x - xc.x, pv.y - xc.y, pv.z - xc.z, pv.w - xc.w);
#define MIXOUT(dst, m) { \
    float4 mm = *(const float4*)((m) + c); \
    float4 r_ = make_float4(fmaf(dx.x, mm.x, xc.x), fmaf(dx.y, mm.y, xc.y), \
                            fmaf(dx.z, mm.z, xc.z), fmaf(dx.w, mm.w, xc.w)); \
    *(float4*)((dst) + off) = r_; }
    MIXOUT(oxr, mr) MIXOUT(oxw, mw) MIXOUT(oxk, mk)
    MIXOUT(oxv, mv) MIXOUT(oxa, ma) MIXOUT(oxg, mg)
#undef MIXOUT
}

// ---------------- K2: bf16x3 mma.sync NT GEMM, ldmatrix fragments ---------------------
#define SROW 20
#define STAGE_U32 (128 * SROW)

#define MMA_BF16(ac, a0, a1, a2, a3, b0, b1) \
    asm volatile("mma.sync.aligned.m16n8k16.row.col.f32.bf16.bf16.f32 " \
        "{%0,%1,%2,%3},{%4,%5,%6,%7},{%8,%9},{%0,%1,%2,%3};" \
        : "+f"((ac)[0]), "+f"((ac)[1]), "+f"((ac)[2]), "+f"((ac)[3]) \
        : "r"(a0), "r"(a1), "r"(a2), "r"(a3), "r"(b0), "r"(b1))

#define LDSM4(r0, r1, r2, r3, addr) \
    asm volatile("ldmatrix.sync.aligned.m8n8.x4.shared.b16 {%0,%1,%2,%3},[%4];" \
        : "=r"(r0), "=r"(r1), "=r"(r2), "=r"(r3) : "r"(addr));

__global__ void __launch_bounds__(256) k_gemm_mma(const float* __restrict__ A,
                                                  const float* __restrict__ B,
                                                  float* __restrict__ Cg) {
    extern __shared__ u32 smem_dyn[];
    const int bm = blockIdx.y * 128;
    const int bn = blockIdx.x * 128;
    const int tid = threadIdx.x;
    const int wid = tid >> 5;
    const int lane = tid & 31;
    const int wm = (wid & 1) * 64;
    const int wn = (wid >> 1) * 32;
    const int g = lane >> 2;
    const int tg = lane & 3;

    // ldmatrix per-lane address offset: row = lane&15 within tile, half = lane>>4
    const u32 lds_rowoff = (u32)((((lane & 15) * SROW) + (lane >> 4) * 4) * 4);
    const u32 smem_base_u = (u32)__cvta_generic_to_shared(smem_dyn);

    float acc[4][4][4];
#pragma unroll
    for (int mt = 0; mt < 4; mt++)
#pragma unroll
        for (int nt = 0; nt < 4; nt++)
#pragma unroll
            for (int q = 0; q < 4; q++) acc[mt][nt][q] = 0.f;

    float2 aPre[8], bPre[8];
#define LDG_CHUNK(cc) { \
    _Pragma("unroll") \
    for (int i = 0; i < 8; i++) { \
        const int p = i * 256 + tid; \
        const int row = p >> 4; \
        const int kk = (p & 15) * 2; \
        aPre[i] = *(const float2*)(A + (size_t)(bm + row) * C + (cc) * 32 + kk); \
        bPre[i] = *(const float2*)(B + (size_t)(bn + row) * C + (cc) * 32 + kk); \
    } }

#define SPLIT_STORE(f2, Hbuf, Lbuf, w) { \
    u32 bx_ = __float_as_uint((f2).x), by_ = __float_as_uint((f2).y); \
    u32 hx_ = bx_ & 0xFFFF0000u, hy_ = by_ & 0xFFFF0000u; \
    (Hbuf)[w] = (hx_ >> 16) | hy_; \
    float lx_ = (f2).x - __uint_as_float(hx_); \
    float ly_ = (f2).y - __uint_as_float(hy_); \
    u32 lp_; \
    asm("cvt.rn.satfinite.bf16x2.f32 %0, %1, %2;" : "=r"(lp_) : "f"(ly_), "f"(lx_)); \
    (Lbuf)[w] = lp_; }

#define STS_CHUNK(st) { \
    u32* Ah_ = smem_dyn + (st) * 4 * STAGE_U32; \
    u32* Al_ = Ah_ + STAGE_U32; \
    u32* Bh_ = Al_ + STAGE_U32; \
    u32* Bl_ = Bh_ + STAGE_U32; \
    _Pragma("unroll") \
    for (int i = 0; i < 8; i++) { \
        const int p = i * 256 + tid; \
        const int row = p >> 4; \
        const int colw = p & 15; \
        const u32 w_ = (u32)(row * SROW + colw); \
        SPLIT_STORE(aPre[i], Ah_, Al_, w_) \
        SPLIT_STORE(bPre[i], Bh_, Bl_, w_) \
    } }

    LDG_CHUNK(0)
    STS_CHUNK(0)
    __syncthreads();
    LDG_CHUNK(1)

    const int NCHUNK = C / 32;
    for (int c = 0; c < NCHUNK; c++) {
        const u32 stage_b = smem_base_u + (u32)(c & 1) * (4 * STAGE_U32 * 4);
        const u32 ah_b = stage_b;
        const u32 al_b = stage_b + STAGE_U32 * 4;
        const u32 bh_b = stage_b + 2 * STAGE_U32 * 4;
        const u32 bl_b = stage_b + 3 * STAGE_U32 * 4;

        if (c + 1 < NCHUNK) {
            STS_CHUNK((c + 1) & 1)
        }
        if (c + 2 < NCHUNK) LDG_CHUNK(c + 2)

#pragma unroll
        for (int k16 = 0; k16 < 2; k16++) {
            const u32 koff = (u32)(k16 * 8 * 4);

            u32 aH[4][4], aL[4][4];
#pragma unroll
            for (int mt = 0; mt < 4; mt++) {
                const u32 tile_off = (u32)((wm + mt * 16) * SROW * 4) + koff + lds_rowoff;
                LDSM4(aH[mt][0], aH[mt][1], aH[mt][2], aH[mt][3], ah_b + tile_off)
                LDSM4(aL[mt][0], aL[mt][1], aL[mt][2], aL[mt][3], al_b + tile_off)
            }
            u32 bH[2][4], bL[2][4];
#pragma unroll
            for (int ntp = 0; ntp < 2; ntp++) {
                const u32 tile_off = (u32)((wn + ntp * 16) * SROW * 4) + koff + lds_rowoff;
                LDSM4(bH[ntp][0], bH[ntp][1], bH[ntp][2], bH[ntp][3], bh_b + tile_off)
                LDSM4(bL[ntp][0], bL[ntp][1], bL[ntp][2], bL[ntp][3], bl_b + tile_off)
            }
            // hi*hi
#pragma unroll
            for (int mt = 0; mt < 4; mt++)
#pragma unroll
                for (int nt = 0; nt < 4; nt++)
                    MMA_BF16(acc[mt][nt], aH[mt][0], aH[mt][1], aH[mt][2], aH[mt][3],
                             bH[nt >> 1][nt & 1], bH[nt >> 1][2 + (nt & 1)]);
            // hi*lo
#pragma unroll
            for (int mt = 0; mt < 4; mt++)
#pragma unroll
                for (int nt = 0; nt < 4; nt++)
                    MMA_BF16(acc[mt][nt], aH[mt][0], aH[mt][1], aH[mt][2], aH[mt][3],
                             bL[nt >> 1][nt & 1], bL[nt >> 1][2 + (nt & 1)]);
            // lo*hi
#pragma unroll
            for (int mt = 0; mt < 4; mt++)
#pragma unroll
                for (int nt = 0; nt < 4; nt++)
                    MMA_BF16(acc[mt][nt], aL[mt][0], aL[mt][1], aL[mt][2], aL[mt][3],
                             bH[nt >> 1][nt & 1], bH[nt >> 1][2 + (nt & 1)]);
        }
        __syncthreads();
    }

#pragma unroll
    for (int mt = 0; mt < 4; mt++) {
#pragma unroll
        for (int nt = 0; nt < 4; nt++) {
            const int row = bm + wm + mt * 16 + g;
            const int col = bn + wn + nt * 8 + tg * 2;
            *(float2*)(Cg + (size_t)row * C + col) =
                make_float2(acc[mt][nt][0], acc[mt][nt][1]);
            *(float2*)(Cg + (size_t)(row + 8) * C + col) =
                make_float2(acc[mt][nt][2], acc[mt][nt][3]);
        }
    }
#undef LDG_CHUNK
#undef STS_CHUNK
#undef SPLIT_STORE
}

// ---------------- K3: stage-1 LoRA GEMM ----------------
template <int KO, int ACT>
__global__ void __launch_bounds__(256) k_stage1(const float* __restrict__ X,
                                                const float* __restrict__ W,
                                                float* __restrict__ out) {
    __shared__ float Xs[32][33];
    __shared__ float Ws[32][KO];
    const int t0 = blockIdx.x * 32;
    const int tid = threadIdx.x;
    const int j = tid % KO;
    const int tg = tid / KO;
    const int RPT = 256 / KO;
    const int NT = 32 / RPT;
    float acc[NT];
#pragma unroll
    for (int tt = 0; tt < NT; tt++) acc[tt] = 0.f;

    for (int cb = 0; cb < C; cb += 32) {
#pragma unroll
        for (int i = tid; i < 32 * 32; i += 256)
            Xs[i >> 5][i & 31] = X[(size_t)(t0 + (i >> 5)) * C + cb + (i & 31)];
#pragma unroll
        for (int i = tid; i < 32 * KO; i += 256)
            Ws[i / KO][i % KO] = W[(size_t)(cb + i / KO) * KO + (i % KO)];
        __syncthreads();
#pragma unroll
        for (int cc = 0; cc < 32; cc++) {
            float wv = Ws[cc][j];
#pragma unroll
            for (int tt = 0; tt < NT; tt++)
                acc[tt] = fmaf(Xs[tg * NT + tt][cc], wv, acc[tt]);
        }
        __syncthreads();
    }
#pragma unroll
    for (int tt = 0; tt < NT; tt++) {
        float val = acc[tt];
        if (ACT == 1) val = tanhf(val);
        else if (ACT == 2) val = 1.f / (1.f + expf(-val));
        out[(size_t)(t0 + tg * NT + tt) * KO + j] = val;
    }
}

// ---------------- K4: stage-2 LoRA GEMM + fused epilogue ----------------
template <int KI, int EPI>
__global__ void __launch_bounds__(128) k_stage2(const float* __restrict__ Hh,
                                                const float* __restrict__ W2,
                                                const float* __restrict__ bias,
                                                const float* __restrict__ e1,
                                                const float* __restrict__ e2,
                                                float* __restrict__ out) {
    __shared__ float Hs[16][KI];
    const int tb = blockIdx.y * 16;
    const int o = blockIdx.x * 128 + threadIdx.x;
    for (int i = threadIdx.x; i < 16 * KI; i += 128)
        Hs[i / KI][i % KI] = Hh[(size_t)(tb + i / KI) * KI + (i % KI)];
    __syncthreads();
    float acc[16];
#pragma unroll
    for (int t = 0; t < 16; t++) acc[t] = 0.f;
#pragma unroll 8
    for (int cdx = 0; cdx < KI; cdx++) {
        float wv = W2[(size_t)cdx * C + o];
#pragma unroll
        for (int t = 0; t < 16; t++)
            acc[t] = fmaf(Hs[t][cdx], wv, acc[t]);
    }
    float bv = (EPI == 3) ? 0.f : bias[o];
#pragma unroll
    for (int t = 0; t < 16; t++) {
        size_t idx = (size_t)(tb + t) * C + o;
        float zv = acc[t] + bv;
        float res;
        if (EPI == 0) {
            float xn = -zv;
            float sp = (xn > 20.f) ? xn : log1pf(expf(xn));
            res = expf(-expf(-sp - 0.5f));
        } else if (EPI == 1) {
            res = 1.f / (1.f + expf(-zv));
        } else if (EPI == 2) {
            float sg = 1.f / (1.f + expf(-zv));
            float vr = e1[idx];
            res = fmaf(e2[idx] - vr, sg, vr);
        } else {
            res = zv;
        }
        out[idx] = res;
    }
}

// ---------------- K5: scan-input prep ----------------
__global__ void k_prep(const float* __restrict__ kin, const float* __restrict__ ain,
                       const float* __restrict__ kkw, const float* __restrict__ kaw,
                       float* __restrict__ aab, float* __restrict__ bbb,
                       float* __restrict__ kadj) {
    const int t = blockIdx.x;
    const int tid = threadIdx.x;
    const int cbase = tid * 4;
    const size_t idx = (size_t)t * C + cbase;
    float4 kv = *(const float4*)(kin + idx);
    float4 av = *(const float4*)(ain + idx);
    float4 kw = *(const float4*)(kkw + cbase);
    float4 aw = *(const float4*)(kaw + cbase);
    float4 kk = make_float4(kv.x * kw.x, kv.y * kw.y, kv.z * kw.z, kv.w * kw.w);
    float ss = kk.x * kk.x + kk.y * kk.y + kk.z * kk.z + kk.w * kk.w;
#pragma unroll
    for (int off = 8; off > 0; off >>= 1)
        ss += __shfl_xor_sync(0xffffffffu, ss, off);
    float inv = 1.f / fmaxf(sqrtf(ss), 1e-12f);
    float4 kn = make_float4(kk.x * inv, kk.y * inv, kk.z * inv, kk.w * inv);
    *(float4*)(aab + idx) = make_float4(-kn.x, -kn.y, -kn.z, -kn.w);
    *(float4*)(bbb + idx) = make_float4(kn.x * av.x, kn.y * av.y, kn.z * av.z, kn.w * av.w);
    *(float4*)(kadj + idx) = make_float4(
        kv.x * fmaf(av.x - 1.f, aw.x, 1.f),
        kv.y * fmaf(av.y - 1.f, aw.y, 1.f),
        kv.z * fmaf(av.z - 1.f, aw.z, 1.f),
        kv.w * fmaf(av.w - 1.f, aw.w, 1.f));
}

// ---------------- K6: RWKV-7 scan — pipelined LDS, 4 v-rows/block ----------------------
union U8 { float f[8]; u64 u[4]; float4 v[2]; };

#define RING_SLOTS 16
#define CHUNK 8

__global__ void __launch_bounds__(32) k_scan(const float* __restrict__ rb,
                                             const float* __restrict__ ewb,
                                             const float* __restrict__ aab,
                                             const float* __restrict__ bbb,
                                             const float* __restrict__ kb,
                                             const float* __restrict__ vb,
                                             const float* __restrict__ S0,
                                             float* __restrict__ y) {
    __shared__ float ring[RING_SLOTS][6 * HS];
    const int h  = blockIdx.x;
    const int vg = blockIdx.y;
    const int tid = threadIdx.x;
    const int jg = tid & 7;
    const int vr = tid >> 3;
    const int vrow = vg * 4 + vr;
    const int jb = jg * 8;

    U8 S;
    S.v[0] = *(const float4*)(S0 + (size_t)h * HS * HS + (size_t)vrow * HS + jb);
    S.v[1] = *(const float4*)(S0 + (size_t)h * HS * HS + (size_t)vrow * HS + jb + 4);

    const int off16 = (tid & 15) << 2;
    const int arr0 = tid >> 4;
    const int arr1 = arr0 + 2;
    const int arr2 = arr0 + 4;
    const float* s0 = (arr0 == 0 ? rb  : ewb) + (size_t)h * HS + off16;
    const float* s1 = (arr1 == 2 ? aab : bbb) + (size_t)h * HS + off16;
    const float* s2 = (arr2 == 4 ? kb  : vb ) + (size_t)h * HS + off16;
    unsigned base_u = (unsigned)__cvta_generic_to_shared(&ring[0][0]);
    const unsigned d0 = base_u + (unsigned)(arr0 * HS + off16) * 4u;
    const unsigned d1 = base_u + (unsigned)(arr1 * HS + off16) * 4u;
    const unsigned d2 = base_u + (unsigned)(arr2 * HS + off16) * 4u;

#define ISSUE_CHUNK(cb) { \
    _Pragma("unroll") \
    for (int s_ = 0; s_ < CHUNK; s_++) { \
        int st_ = (cb) * CHUNK + s_; \
        int slot_ = st_ & (RING_SLOTS - 1); \
        if (st_ >= T) st_ = T - 1; \
        size_t so_ = (size_t)st_ * C; \
        unsigned sb_ = (unsigned)slot_ * (6 * HS * 4); \
        cp16(d0 + sb_, s0 + so_); \
        cp16(d1 + sb_, s1 + so_); \
        cp16(d2 + sb_, s2 + so_); \
    } \
    asm volatile("cp.async.commit_group;"); }

#define LOADSTEP(RV, EV, AV, BV, KV, VT, tt) { \
    const float* sp_ = &ring[(tt) & (RING_SLOTS - 1)][0]; \
    RV.v[0] = *(const float4*)&sp_[0 * HS + jb]; \
    RV.v[1] = *(const float4*)&sp_[0 * HS + jb + 4]; \
    EV.v[0] = *(const float4*)&sp_[1 * HS + jb]; \
    EV.v[1] = *(const float4*)&sp_[1 * HS + jb + 4]; \
    AV.v[0] = *(const float4*)&sp_[2 * HS + jb]; \
    AV.v[1] = *(const float4*)&sp_[2 * HS + jb + 4]; \
    BV.v[0] = *(const float4*)&sp_[3 * HS + jb]; \
    BV.v[1] = *(const float4*)&sp_[3 * HS + jb + 4]; \
    KV.v[0] = *(const float4*)&sp_[4 * HS + jb]; \
    KV.v[1] = *(const float4*)&sp_[4 * HS + jb + 4]; \
    VT = sp_[5 * HS + vrow]; }

#define COMPUTE(RV, EV, AV, BV, KV, VT, t) { \
    if ((t) > 0 && jg == 0) \
        y[(size_t)((t) - 1) * C + ybase] = (o_l + os1) + (os2 + os3); \
    u64 sacc0 = mul2(S.u[0], AV.u[0]); \
    u64 sacc1 = mul2(S.u[1], AV.u[1]); \
    sacc0 = fma2(S.u[2], AV.u[2], sacc0); \
    sacc1 = fma2(S.u[3], AV.u[3], sacc1); \
    float2 sp2 = unpack2(add2(sacc0, sacc1)); \
    float sal = sp2.x + sp2.y; \
    float sA = __shfl_xor_sync(0xffffffffu, sal, 1); \
    float sB = __shfl_xor_sync(0xffffffffu, sal, 2); \
    float sC = __shfl_xor_sync(0xffffffffu, sal, 4); \
    u64 vt2 = pack2(VT, VT); \
    u64 pre[4]; \
    _Pragma("unroll") \
    for (int q = 0; q < 4; q++) \
        pre[q] = fma2(S.u[q], EV.u[q], mul2(vt2, KV.u[q])); \
    float sD = __shfl_xor_sync(0xffffffffu, sA, 2); \
    float sE = __shfl_xor_sync(0xffffffffu, sA, 4); \
    float sF = __shfl_xor_sync(0xffffffffu, sB, 4); \
    float sG = __shfl_xor_sync(0xffffffffu, sD, 4); \
    float sa = ((sal + sA) + (sB + sD)) + ((sC + sE) + (sF + sG)); \
    u64 sa2 = pack2(sa, sa); \
    u64 oa0 = 0ull, oa1 = 0ull; \
    _Pragma("unroll") \
    for (int q = 0; q < 4; q += 2) { \
        S.u[q]     = fma2(sa2, BV.u[q],     pre[q]); \
        S.u[q + 1] = fma2(sa2, BV.u[q + 1], pre[q + 1]); \
        oa0 = fma2(S.u[q],     RV.u[q],     oa0); \
        oa1 = fma2(S.u[q + 1], RV.u[q + 1], oa1); \
    } \
    float2 op2 = unpack2(add2(oa0, oa1)); \
    float ol = op2.x + op2.y; \
    float o1 = __shfl_xor_sync(0xffffffffu, ol, 1); \
    float o2p = ol + o1; \
    float o2 = __shfl_xor_sync(0xffffffffu, o2p, 2); \
    float o4p = o2p + o2; \
    float o4 = __shfl_xor_sync(0xffffffffu, o4p, 4); \
    o_l = 0.f; os3 = 0.f; os2 = o4p; os1 = o4; }

    ISSUE_CHUNK(0)
    ISSUE_CHUNK(1)

    float o_l = 0.f, os1 = 0.f, os2 = 0.f, os3 = 0.f;
    const size_t ybase = (size_t)h * HS + vrow;
    const int NCH = T / CHUNK;

    U8 R0, E0, A0, B0, K0, R1, E1, A1, B1, K1;
    float vt0, vt1;

    for (int c = 0; c < NCH; c++) {
        asm volatile("cp.async.wait_group 1;");
        __syncwarp();
        const int tb = c * CHUNK;

        LOADSTEP(R0, E0, A0, B0, K0, vt0, tb)
#pragma unroll
        for (int s = 0; s < CHUNK; s += 2) {
            if (s + 1 < CHUNK) LOADSTEP(R1, E1, A1, B1, K1, vt1, tb + s + 1)
            COMPUTE(R0, E0, A0, B0, K0, vt0, tb + s)
            if (s + 2 < CHUNK) LOADSTEP(R0, E0, A0, B0, K0, vt0, tb + s + 2)
            COMPUTE(R1, E1, A1, B1, K1, vt1, tb + s + 1)
        }

        ISSUE_CHUNK(c + 2)
    }
    if (jg == 0)
        y[(size_t)(T - 1) * C + ybase] = (o_l + os1) + (os2 + os3);
#undef ISSUE_CHUNK
#undef LOADSTEP
#undef COMPUTE
}

// ---------------- K7: GroupNorm + bonus + gate ----------------
__global__ void k_gn(const float* __restrict__ y, const float* __restrict__ r,
                     const float* __restrict__ kadj, const float* __restrict__ v,
                     const float* __restrict__ gg, const float* __restrict__ rk,
                     const float* __restrict__ lnw, const float* __restrict__ lnb,
                     float* __restrict__ z) {
    const int t = blockIdx.x;
    const int tid = threadIdx.x;
    const int cbase = tid * 4;
    const size_t idx = (size_t)t * C + cbase;
    float4 yv = *(const float4*)(y + idx);
    float s1 = yv.x + yv.y + yv.z + yv.w;
    float s2 = yv.x * yv.x + yv.y * yv.y + yv.z * yv.z + yv.w * yv.w;
    float4 rv = *(const float4*)(r + idx);
    float4 kv = *(const float4*)(kadj + idx);
    float4 rkv = *(const float4*)(rk + cbase);
    float s3 = rv.x * kv.x * rkv.x + rv.y * kv.y * rkv.y +
               rv.z * kv.z * rkv.z + rv.w * kv.w * rkv.w;
#pragma unroll
    for (int off = 8; off > 0; off >>= 1) {
        s1 += __shfl_xor_sync(0xffffffffu, s1, off);
        s2 += __shfl_xor_sync(0xffffffffu, s2, off);
        s3 += __shfl_xor_sync(0xffffffffu, s3, off);
    }
    const float mu = s1 * (1.f / HS);
    const float var = s2 * (1.f / HS) - mu * mu;
    const float inv = rsqrtf(var + EPS_GN);
    float4 vv = *(const float4*)(v + idx);
    float4 gv = *(const float4*)(gg + idx);
    float4 lw = *(const float4*)(lnw + cbase);
    float4 lb = *(const float4*)(lnb + cbase);
    float4 res;
    res.x = (fmaf((yv.x - mu) * inv, lw.x, lb.x) + s3 * vv.x) * gv.x;
    res.y = (fmaf((yv.y - mu) * inv, lw.y, lb.y) + s3 * vv.y) * gv.y;
    res.z = (fmaf((yv.z - mu) * inv, lw.z, lb.z) + s3 * vv.z) * gv.z;
    res.w = (fmaf((yv.w - mu) * inv, lw.w, lb.w) + s3 * vv.w) * gv.w;
    *(float4*)(z + idx) = res;
}

// ---------------- launch ----------------
extern "C" void kernel_launch(void* const* d_in, const int* in_sizes, int n_in,
                              void* d_out, int out_size) {
    const float* x       = (const float*)d_in[0];
    const float* v_first = (const float*)d_in[1];
    const float* x_prev  = (const float*)d_in[2];
    const float* S0      = (const float*)d_in[3];
    const float* m_r = (const float*)d_in[4];
    const float* m_w = (const float*)d_in[5];
    const float* m_k = (const float*)d_in[6];
    const float* m_v = (const float*)d_in[7];
    const float* m_a = (const float*)d_in[8];
    const float* m_g = (const float*)d_in[9];

    const float *w0, *w1, *w2, *a0, *a1, *a2, *v0, *v1, *v2, *g1, *g2, *k_k, *k_a, *r_k;
    if (in_sizes[11] == C) {
        w0 = (const float*)d_in[10]; a0 = (const float*)d_in[11];
        v0 = (const float*)d_in[12]; k_k = (const float*)d_in[13];
        k_a = (const float*)d_in[14];
        w1 = (const float*)d_in[15]; w2 = (const float*)d_in[16];
        a1 = (const float*)d_in[17]; a2 = (const float*)d_in[18];
        v1 = (const float*)d_in[19]; v2 = (const float*)d_in[20];
        g1 = (const float*)d_in[21]; g2 = (const float*)d_in[22];
        r_k = (const float*)d_in[23];
    } else {
        w0 = (const float*)d_in[10]; w1 = (const float*)d_in[11];
        w2 = (const float*)d_in[12];
        a0 = (const float*)d_in[13]; a1 = (const float*)d_in[14];
        a2 = (const float*)d_in[15];
        v0 = (const float*)d_in[16]; v1 = (const float*)d_in[17];
        v2 = (const float*)d_in[18];
        g1 = (const float*)d_in[19]; g2 = (const float*)d_in[20];
        k_k = (const float*)d_in[21]; k_a = (const float*)d_in[22];
        r_k = (const float*)d_in[23];
    }

    const float* Wr = (const float*)d_in[24];
    const float* Wk = (const float*)d_in[25];
    const float* Wv = (const float*)d_in[26];
    const float* Wo = (const float*)d_in[27];
    const float* lnw = (const float*)d_in[28];
    const float* lnb = (const float*)d_in[29];
    const int*   cu  = (const int*)d_in[30];
    const int ncu = in_sizes[30];
    float* out = (float*)d_out;

    float* s = nullptr;
    cudaGetSymbolAddress((void**)&s, g_scratch);
    const size_t P = (size_t)T * C;
    float* xr = s;          float* xw = s + P;      float* xk = s + 2 * P;
    float* xv = s + 3 * P;  float* xa = s + 4 * P;  float* xg = s + 5 * P;
    float* rb = s + 6 * P;  float* kb = s + 7 * P;  float* vbuf = s + 8 * P;
    float* ewb = s + 9 * P; float* ab = s + 10 * P; float* gbuf = s + 11 * P;
    float* aab = s + 12 * P; float* bbb = s + 13 * P; float* kadj = s + 14 * P;
    float* yb = s + 15 * P;  float* zb = s + 16 * P;
    float* hw = s + 17 * P;
    float* ha = hw + (size_t)T * 64;
    float* hv = ha + (size_t)T * 64;
    float* hg = hv + (size_t)T * 32;

    const int GEMM_SMEM = 2 * 4 * STAGE_U32 * 4;
    static int smem_set = 0;
    if (!smem_set) {
        cudaFuncSetAttribute(k_gemm_mma, cudaFuncAttributeMaxDynamicSharedMemorySize,
                             GEMM_SMEM);
        smem_set = 1;
    }

    k_shift_mix<<<T, 256>>>(x, x_prev, cu, ncu, m_r, m_w, m_k, m_v, m_a, m_g,
                            xr, xw, xk, xv, xa, xg);

    dim3 gemm_grid(C / 128, T / 128);
    k_gemm_mma<<<gemm_grid, 256, GEMM_SMEM>>>(xr, Wr, rb);
    k_gemm_mma<<<gemm_grid, 256, GEMM_SMEM>>>(xk, Wk, kb);
    k_gemm_mma<<<gemm_grid, 256, GEMM_SMEM>>>(xv, Wv, vbuf);

    k_stage1<64, 1><<<T / 32, 256>>>(xw, w1, hw);
    k_stage1<64, 0><<<T / 32, 256>>>(xa, a1, ha);
    k_stage1<32, 0><<<T / 32, 256>>>(xv, v1, hv);
    k_stage1<128, 2><<<T / 32, 256>>>(xg, g1, hg);

    dim3 s2grid(C / 128, T / 16);
    k_stage2<64, 0><<<s2grid, 128>>>(hw, w2, w0, nullptr, nullptr, ewb);
    k_stage2<64, 1><<<s2grid, 128>>>(ha, a2, a0, nullptr, nullptr, ab);
    k_stage2<32, 2><<<s2grid, 128>>>(hv, v2, v0, vbuf, v_first, vbuf);
    k_stage2<128, 3><<<s2grid, 128>>>(hg, g2, nullptr, nullptr, nullptr, gbuf);

    k_prep<<<T, 256>>>(kb, ab, k_k, k_a, aab, bbb, kadj);

    k_scan<<<dim3(NH, 16), 32>>>(rb, ewb, aab, bbb, kadj, vbuf, S0, yb);

    k_gn<<<T, 256>>>(yb, rb, kadj, vbuf, gbuf, r_k, lnw, lnb, zb);

    k_gemm_mma<<<gemm_grid, 256, GEMM_SMEM>>>(zb, Wo, out);
}

// round 13
// speedup vs baseline: 1.0071x; 1.0071x over previous
#include <cuda_runtime.h>
#include <math.h>

static const int T  = 2048;
static const int C  = 1024;
static const int NH = 16;
static const int HS = 64;
#define EPS_GN 0.00064f

typedef unsigned long long u64;
typedef unsigned int u32;

// ---------------- f32x2 packed helpers ----------------
__device__ __forceinline__ u64 fma2(u64 a, u64 b, u64 c) {
    u64 d; asm("fma.rn.f32x2 %0, %1, %2, %3;" : "=l"(d) : "l"(a), "l"(b), "l"(c)); return d;
}
__device__ __forceinline__ u64 mul2(u64 a, u64 b) {
    u64 d; asm("mul.rn.f32x2 %0, %1, %2;" : "=l"(d) : "l"(a), "l"(b)); return d;
}
__device__ __forceinline__ u64 add2(u64 a, u64 b) {
    u64 d; asm("add.rn.f32x2 %0, %1, %2;" : "=l"(d) : "l"(a), "l"(b)); return d;
}
__device__ __forceinline__ u64 pack2(float lo, float hi) {
    u64 d; asm("mov.b64 %0, {%1, %2};" : "=l"(d) : "f"(lo), "f"(hi)); return d;
}
__device__ __forceinline__ float2 unpack2(u64 v) {
    float2 r; asm("mov.b64 {%0, %1}, %2;" : "=f"(r.x), "=f"(r.y) : "l"(v)); return r;
}
__device__ __forceinline__ void cp16(unsigned s, const float* g) {
    asm volatile("cp.async.ca.shared.global [%0], [%1], 16;" :: "r"(s), "l"(g));
}

// ---------------- scratch ----------------
__device__ float g_scratch[(size_t)17 * 2048 * 1024 + (size_t)2048 * 288];

// ---------------- K1: token shift + 6-way mix ----------------
__global__ void k_shift_mix(const float* __restrict__ x, const float* __restrict__ x_prev,
                            const int* __restrict__ cu, int ncu,
                            const float* __restrict__ mr, const float* __restrict__ mw,
                            const float* __restrict__ mk, const float* __restrict__ mv,
                            const float* __restrict__ ma, const float* __restrict__ mg,
                            float* __restrict__ oxr, float* __restrict__ oxw,
                            float* __restrict__ oxk, float* __restrict__ oxv,
                            float* __restrict__ oxa, float* __restrict__ oxg) {
    const int t = blockIdx.x;
    int kind = (t == 0) ? 1 : 0;
    int prow = 0;
    for (int i = 0; i + 1 < ncu; i++) if (cu[i] == t) { kind = 2; prow = i; }
    const int c = threadIdx.x * 4;
    const size_t off = (size_t)t * C + c;
    float4 xc = *(const float4*)(x + off);
    float4 pv;
    if (kind == 0)      pv = *(const float4*)(x + off - C);
    else if (kind == 2) pv = *(const float4*)(x_prev + (size_t)prow * C + c);
    else                pv = make_float4(0.f, 0.f, 0.f, 0.f);
    float4 dx = make_float4(pv.x - xc.x, pv.y - xc.y, pv.z - xc.z, pv.w - xc.w);
#define MIXOUT(dst, m) { \
    float4 mm = *(const float4*)((m) + c); \
    float4 r_ = make_float4(fmaf(dx.x, mm.x, xc.x), fmaf(dx.y, mm.y, xc.y), \
                            fmaf(dx.z, mm.z, xc.z), fmaf(dx.w, mm.w, xc.w)); \
    *(float4*)((dst) + off) = r_; }
    MIXOUT(oxr, mr) MIXOUT(oxw, mw) MIXOUT(oxk, mk)
    MIXOUT(oxv, mv) MIXOUT(oxa, ma) MIXOUT(oxg, mg)
#undef MIXOUT
}

// ---------------- K2: bf16x3 mma.sync NT GEMM, double-buffered, SROW=20 ---------------
#define SROW 20
#define STAGE_U32 (128 * SROW)

#define MMA_BF16(ac, av, bv) \
    asm volatile("mma.sync.aligned.m16n8k16.row.col.f32.bf16.bf16.f32 " \
        "{%0,%1,%2,%3},{%4,%5,%6,%7},{%8,%9},{%0,%1,%2,%3};" \
        : "+f"((ac)[0]), "+f"((ac)[1]), "+f"((ac)[2]), "+f"((ac)[3]) \
        : "r"((av)[0]), "r"((av)[1]), "r"((av)[2]), "r"((av)[3]), \
          "r"((bv)[0]), "r"((bv)[1]))

__global__ void __launch_bounds__(256) k_gemm_mma(const float* __restrict__ A,
                                                  const float* __restrict__ B,
                                                  float* __restrict__ Cg) {
    extern __shared__ u32 smem_dyn[];
    const int bm = blockIdx.y * 128;
    const int bn = blockIdx.x * 128;
    const int tid = threadIdx.x;
    const int wid = tid >> 5;
    const int lane = tid & 31;
    const int wm = (wid & 1) * 64;
    const int wn = (wid >> 1) * 32;
    const int g = lane >> 2;
    const int tg = lane & 3;

    float acc[4][4][4];
#pragma unroll
    for (int mt = 0; mt < 4; mt++)
#pragma unroll
        for (int nt = 0; nt < 4; nt++)
#pragma unroll
            for (int q = 0; q < 4; q++) acc[mt][nt][q] = 0.f;

    float2 aPre[8], bPre[8];
#define LDG_CHUNK(cc) { \
    _Pragma("unroll") \
    for (int i = 0; i < 8; i++) { \
        const int p = i * 256 + tid; \
        const int row = p >> 4; \
        const int kk = (p & 15) * 2; \
        aPre[i] = *(const float2*)(A + (size_t)(bm + row) * C + (cc) * 32 + kk); \
        bPre[i] = *(const float2*)(B + (size_t)(bn + row) * C + (cc) * 32 + kk); \
    } }

#define SPLIT_STORE(f2, Hbuf, Lbuf, w) { \
    u32 bx_ = __float_as_uint((f2).x), by_ = __float_as_uint((f2).y); \
    u32 hx_ = bx_ & 0xFFFF0000u, hy_ = by_ & 0xFFFF0000u; \
    (Hbuf)[w] = (hx_ >> 16) | hy_; \
    float lx_ = (f2).x - __uint_as_float(hx_); \
    float ly_ = (f2).y - __uint_as_float(hy_); \
    u32 lp_; \
    asm("cvt.rn.satfinite.bf16x2.f32 %0, %1, %2;" : "=r"(lp_) : "f"(ly_), "f"(lx_)); \
    (Lbuf)[w] = lp_; }

#define STS_CHUNK(st) { \
    u32* Ah_ = smem_dyn + (st) * 4 * STAGE_U32; \
    u32* Al_ = Ah_ + STAGE_U32; \
    u32* Bh_ = Al_ + STAGE_U32; \
    u32* Bl_ = Bh_ + STAGE_U32; \
    _Pragma("unroll") \
    for (int i = 0; i < 8; i++) { \
        const int p = i * 256 + tid; \
        const int row = p >> 4; \
        const int colw = p & 15; \
        const u32 w_ = (u32)(row * SROW + colw); \
        SPLIT_STORE(aPre[i], Ah_, Al_, w_) \
        SPLIT_STORE(bPre[i], Bh_, Bl_, w_) \
    } }

    LDG_CHUNK(0)
    STS_CHUNK(0)
    __syncthreads();
    LDG_CHUNK(1)

    const int NCHUNK = C / 32;
    for (int c = 0; c < NCHUNK; c++) {
        const u32* Ah = smem_dyn + (c & 1) * 4 * STAGE_U32;
        const u32* Al = Ah + STAGE_U32;
        const u32* Bh = Al + STAGE_U32;
        const u32* Bl = Bh + STAGE_U32;

        if (c + 1 < NCHUNK) {
            STS_CHUNK((c + 1) & 1)
        }
        if (c + 2 < NCHUNK) LDG_CHUNK(c + 2)

#pragma unroll
        for (int k16 = 0; k16 < 2; k16++) {
            const int colb = k16 * 8 + tg;

            u32 aH[4][4];
#pragma unroll
            for (int mt = 0; mt < 4; mt++) {
                const int base = (wm + mt * 16 + g) * SROW + colb;
                aH[mt][0] = Ah[base];
                aH[mt][1] = Ah[base + 8 * SROW];
                aH[mt][2] = Ah[base + 4];
                aH[mt][3] = Ah[base + 8 * SROW + 4];
            }
            u32 bH[4][2];
#pragma unroll
            for (int nt = 0; nt < 4; nt++) {
                const int base = (wn + nt * 8 + g) * SROW + colb;
                bH[nt][0] = Bh[base];
                bH[nt][1] = Bh[base + 4];
            }
#pragma unroll
            for (int mt = 0; mt < 4; mt++)
#pragma unroll
                for (int nt = 0; nt < 4; nt++)
                    MMA_BF16(acc[mt][nt], aH[mt], bH[nt]);

            u32 bL[4][2];
#pragma unroll
            for (int nt = 0; nt < 4; nt++) {
                const int base = (wn + nt * 8 + g) * SROW + colb;
                bL[nt][0] = Bl[base];
                bL[nt][1] = Bl[base + 4];
            }
#pragma unroll
            for (int mt = 0; mt < 4; mt++)
#pragma unroll
                for (int nt = 0; nt < 4; nt++)
                    MMA_BF16(acc[mt][nt], aH[mt], bL[nt]);

            u32 aL[4][4];
#pragma unroll
            for (int mt = 0; mt < 4; mt++) {
                const int base = (wm + mt * 16 + g) * SROW + colb;
                aL[mt][0] = Al[base];
                aL[mt][1] = Al[base + 8 * SROW];
                aL[mt][2] = Al[base + 4];
                aL[mt][3] = Al[base + 8 * SROW + 4];
            }
#pragma unroll
            for (int mt = 0; mt < 4; mt++)
#pragma unroll
                for (int nt = 0; nt < 4; nt++)
                    MMA_BF16(acc[mt][nt], aL[mt], bH[nt]);
        }
        __syncthreads();
    }

#pragma unroll
    for (int mt = 0; mt < 4; mt++) {
#pragma unroll
        for (int nt = 0; nt < 4; nt++) {
            const int row = bm + wm + mt * 16 + g;
            const int col = bn + wn + nt * 8 + tg * 2;
            *(float2*)(Cg + (size_t)row * C + col) =
                make_float2(acc[mt][nt][0], acc[mt][nt][1]);
            *(float2*)(Cg + (size_t)(row + 8) * C + col) =
                make_float2(acc[mt][nt][2], acc[mt][nt][3]);
        }
    }
#undef LDG_CHUNK
#undef STS_CHUNK
#undef SPLIT_STORE
}

// ---------------- K3: stage-1 LoRA GEMM ----------------
template <int KO, int ACT>
__global__ void __launch_bounds__(256) k_stage1(const float* __restrict__ X,
                                                const float* __restrict__ W,
                                                float* __restrict__ out) {
    __shared__ float Xs[32][33];
    __shared__ float Ws[32][KO];
    const int t0 = blockIdx.x * 32;
    const int tid = threadIdx.x;
    const int j = tid % KO;
    const int tg = tid / KO;
    const int RPT = 256 / KO;
    const int NT = 32 / RPT;
    float acc[NT];
#pragma unroll
    for (int tt = 0; tt < NT; tt++) acc[tt] = 0.f;

    for (int cb = 0; cb < C; cb += 32) {
#pragma unroll
        for (int i = tid; i < 32 * 32; i += 256)
            Xs[i >> 5][i & 31] = X[(size_t)(t0 + (i >> 5)) * C + cb + (i & 31)];
#pragma unroll
        for (int i = tid; i < 32 * KO; i += 256)
            Ws[i / KO][i % KO] = W[(size_t)(cb + i / KO) * KO + (i % KO)];
        __syncthreads();
#pragma unroll
        for (int cc = 0; cc < 32; cc++) {
            float wv = Ws[cc][j];
#pragma unroll
            for (int tt = 0; tt < NT; tt++)
                acc[tt] = fmaf(Xs[tg * NT + tt][cc], wv, acc[tt]);
        }
        __syncthreads();
    }
#pragma unroll
    for (int tt = 0; tt < NT; tt++) {
        float val = acc[tt];
        if (ACT == 1) val = tanhf(val);
        else if (ACT == 2) val = 1.f / (1.f + expf(-val));
        out[(size_t)(t0 + tg * NT + tt) * KO + j] = val;
    }
}

// ---------------- K4: stage-2 LoRA GEMM + fused epilogue ----------------
template <int KI, int EPI>
__global__ void __launch_bounds__(128) k_stage2(const float* __restrict__ Hh,
                                                const float* __restrict__ W2,
                                                const float* __restrict__ bias,
                                                const float* __restrict__ e1,
                                                const float* __restrict__ e2,
                                                float* __restrict__ out) {
    __shared__ float Hs[16][KI];
    const int tb = blockIdx.y * 16;
    const int o = blockIdx.x * 128 + threadIdx.x;
    for (int i = threadIdx.x; i < 16 * KI; i += 128)
        Hs[i / KI][i % KI] = Hh[(size_t)(tb + i / KI) * KI + (i % KI)];
    __syncthreads();
    float acc[16];
#pragma unroll
    for (int t = 0; t < 16; t++) acc[t] = 0.f;
#pragma unroll 8
    for (int cdx = 0; cdx < KI; cdx++) {
        float wv = W2[(size_t)cdx * C + o];
#pragma unroll
        for (int t = 0; t < 16; t++)
            acc[t] = fmaf(Hs[t][cdx], wv, acc[t]);
    }
    float bv = (EPI == 3) ? 0.f : bias[o];
#pragma unroll
    for (int t = 0; t < 16; t++) {
        size_t idx = (size_t)(tb + t) * C + o;
        float zv = acc[t] + bv;
        float res;
        if (EPI == 0) {
            float xn = -zv;
            float sp = (xn > 20.f) ? xn : log1pf(expf(xn));
            res = expf(-expf(-sp - 0.5f));
        } else if (EPI == 1) {
            res = 1.f / (1.f + expf(-zv));
        } else if (EPI == 2) {
            float sg = 1.f / (1.f + expf(-zv));
            float vr = e1[idx];
            res = fmaf(e2[idx] - vr, sg, vr);
        } else {
            res = zv;
        }
        out[idx] = res;
    }
}

// ---------------- K5: scan-input prep ----------------
__global__ void k_prep(const float* __restrict__ kin, const float* __restrict__ ain,
                       const float* __restrict__ kkw, const float* __restrict__ kaw,
                       float* __restrict__ aab, float* __restrict__ bbb,
                       float* __restrict__ kadj) {
    const int t = blockIdx.x;
    const int tid = threadIdx.x;
    const int cbase = tid * 4;
    const size_t idx = (size_t)t * C + cbase;
    float4 kv = *(const float4*)(kin + idx);
    float4 av = *(const float4*)(ain + idx);
    float4 kw = *(const float4*)(kkw + cbase);
    float4 aw = *(const float4*)(kaw + cbase);
    float4 kk = make_float4(kv.x * kw.x, kv.y * kw.y, kv.z * kw.z, kv.w * kw.w);
    float ss = kk.x * kk.x + kk.y * kk.y + kk.z * kk.z + kk.w * kk.w;
#pragma unroll
    for (int off = 8; off > 0; off >>= 1)
        ss += __shfl_xor_sync(0xffffffffu, ss, off);
    float inv = 1.f / fmaxf(sqrtf(ss), 1e-12f);
    float4 kn = make_float4(kk.x * inv, kk.y * inv, kk.z * inv, kk.w * inv);
    *(float4*)(aab + idx) = make_float4(-kn.x, -kn.y, -kn.z, -kn.w);
    *(float4*)(bbb + idx) = make_float4(kn.x * av.x, kn.y * av.y, kn.z * av.z, kn.w * av.w);
    *(float4*)(kadj + idx) = make_float4(
        kv.x * fmaf(av.x - 1.f, aw.x, 1.f),
        kv.y * fmaf(av.y - 1.f, aw.y, 1.f),
        kv.z * fmaf(av.z - 1.f, aw.z, 1.f),
        kv.w * fmaf(av.w - 1.f, aw.w, 1.f));
}

// ---------------- K6: RWKV-7 scan — 4 v-rows/block, parallel 7-shfl reductions --------
union U8 { float f[8]; u64 u[4]; float4 v[2]; };

#define RING_SLOTS 16
#define CHUNK 8

__global__ void __launch_bounds__(32) k_scan(const float* __restrict__ rb,
                                             const float* __restrict__ ewb,
                                             const float* __restrict__ aab,
                                             const float* __restrict__ bbb,
                                             const float* __restrict__ kb,
                                             const float* __restrict__ vb,
                                             const float* __restrict__ S0,
                                             float* __restrict__ y) {
    __shared__ float ring[RING_SLOTS][6 * HS];
    const int h  = blockIdx.x;
    const int vg = blockIdx.y;
    const int tid = threadIdx.x;
    const int jg = tid & 7;
    const int vr = tid >> 3;
    const int vrow = vg * 4 + vr;
    const int jb = jg * 8;

    U8 S;
    S.v[0] = *(const float4*)(S0 + (size_t)h * HS * HS + (size_t)vrow * HS + jb);
    S.v[1] = *(const float4*)(S0 + (size_t)h * HS * HS + (size_t)vrow * HS + jb + 4);

    const int off16 = (tid & 15) << 2;
    const int arr0 = tid >> 4;
    const int arr1 = arr0 + 2;
    const int arr2 = arr0 + 4;
    const float* s0 = (arr0 == 0 ? rb  : ewb) + (size_t)h * HS + off16;
    const float* s1 = (arr1 == 2 ? aab : bbb) + (size_t)h * HS + off16;
    const float* s2 = (arr2 == 4 ? kb  : vb ) + (size_t)h * HS + off16;
    unsigned base_u = (unsigned)__cvta_generic_to_shared(&ring[0][0]);
    const unsigned d0 = base_u + (unsigned)(arr0 * HS + off16) * 4u;
    const unsigned d1 = base_u + (unsigned)(arr1 * HS + off16) * 4u;
    const unsigned d2 = base_u + (unsigned)(arr2 * HS + off16) * 4u;

#define ISSUE_CHUNK(cb) { \
    _Pragma("unroll") \
    for (int s_ = 0; s_ < CHUNK; s_++) { \
        int st_ = (cb) * CHUNK + s_; \
        int slot_ = st_ & (RING_SLOTS - 1); \
        if (st_ >= T) st_ = T - 1; \
        size_t so_ = (size_t)st_ * C; \
        unsigned sb_ = (unsigned)slot_ * (6 * HS * 4); \
        cp16(d0 + sb_, s0 + so_); \
        cp16(d1 + sb_, s1 + so_); \
        cp16(d2 + sb_, s2 + so_); \
    } \
    asm volatile("cp.async.commit_group;"); }

    ISSUE_CHUNK(0)
    ISSUE_CHUNK(1)

    float oprev = 0.f;
    const size_t ybase = (size_t)h * HS + vrow;
    const int NCH = T / CHUNK;

    for (int c = 0; c < NCH; c++) {
        asm volatile("cp.async.wait_group 1;");
        __syncwarp();

#pragma unroll
        for (int s = 0; s < CHUNK; s++) {
            const int t = c * CHUNK + s;
            if (t > 0 && jg == 0)
                y[(size_t)(t - 1) * C + ybase] = oprev;

            const float* sp = &ring[t & (RING_SLOTS - 1)][0];
            U8 Rv, Ev, Av, Bv, Kv;
            Rv.v[0] = *(const float4*)&sp[0 * HS + jb];
            Rv.v[1] = *(const float4*)&sp[0 * HS + jb + 4];
            Ev.v[0] = *(const float4*)&sp[1 * HS + jb];
            Ev.v[1] = *(const float4*)&sp[1 * HS + jb + 4];
            Av.v[0] = *(const float4*)&sp[2 * HS + jb];
            Av.v[1] = *(const float4*)&sp[2 * HS + jb + 4];
            Bv.v[0] = *(const float4*)&sp[3 * HS + jb];
            Bv.v[1] = *(const float4*)&sp[3 * HS + jb + 4];
            Kv.v[0] = *(const float4*)&sp[4 * HS + jb];
            Kv.v[1] = *(const float4*)&sp[4 * HS + jb + 4];
            const float vt = sp[5 * HS + vrow];

            // sa partial over 8 j
            u64 sacc0 = mul2(S.u[0], Av.u[0]);
            u64 sacc1 = mul2(S.u[1], Av.u[1]);
            sacc0 = fma2(S.u[2], Av.u[2], sacc0);
            sacc1 = fma2(S.u[3], Av.u[3], sacc1);
            float2 sp2 = unpack2(add2(sacc0, sacc1));
            float sal = sp2.x + sp2.y;
            // 7 PARALLEL shfls (single shfl latency, no serial chain)
            float x1 = __shfl_xor_sync(0xffffffffu, sal, 1);
            float x2 = __shfl_xor_sync(0xffffffffu, sal, 2);
            float x3 = __shfl_xor_sync(0xffffffffu, sal, 3);
            float x4 = __shfl_xor_sync(0xffffffffu, sal, 4);
            float x5 = __shfl_xor_sync(0xffffffffu, sal, 5);
            float x6 = __shfl_xor_sync(0xffffffffu, sal, 6);
            float x7 = __shfl_xor_sync(0xffffffffu, sal, 7);

            // overlap shfl latency: pre = S*ew + vt*k
            u64 vt2 = pack2(vt, vt);
            u64 pre[4];
#pragma unroll
            for (int q = 0; q < 4; q++)
                pre[q] = fma2(S.u[q], Ev.u[q], mul2(vt2, Kv.u[q]));

            float sa = ((sal + x1) + (x2 + x3)) + ((x4 + x5) + (x6 + x7));
            u64 sa2 = pack2(sa, sa);

            u64 oa0 = 0ull, oa1 = 0ull;
#pragma unroll
            for (int q = 0; q < 4; q += 2) {
                S.u[q]     = fma2(sa2, Bv.u[q],     pre[q]);
                S.u[q + 1] = fma2(sa2, Bv.u[q + 1], pre[q + 1]);
                oa0 = fma2(S.u[q],     Rv.u[q],     oa0);
                oa1 = fma2(S.u[q + 1], Rv.u[q + 1], oa1);
            }
            float2 op2 = unpack2(add2(oa0, oa1));
            float ol = op2.x + op2.y;
            // 7 parallel shfls; sum completes while next step proceeds (store deferred)
            float y1 = __shfl_xor_sync(0xffffffffu, ol, 1);
            float y2 = __shfl_xor_sync(0xffffffffu, ol, 2);
            float y3 = __shfl_xor_sync(0xffffffffu, ol, 3);
            float y4 = __shfl_xor_sync(0xffffffffu, ol, 4);
            float y5 = __shfl_xor_sync(0xffffffffu, ol, 5);
            float y6 = __shfl_xor_sync(0xffffffffu, ol, 6);
            float y7 = __shfl_xor_sync(0xffffffffu, ol, 7);
            oprev = ((ol + y1) + (y2 + y3)) + ((y4 + y5) + (y6 + y7));
        }

        ISSUE_CHUNK(c + 2)
    }
    if (jg == 0)
        y[(size_t)(T - 1) * C + ybase] = oprev;
#undef ISSUE_CHUNK
}

// ---------------- K7: GroupNorm + bonus + gate ----------------
__global__ void k_gn(const float* __restrict__ y, const float* __restrict__ r,
                     const float* __restrict__ kadj, const float* __restrict__ v,
                     const float* __restrict__ gg, const float* __restrict__ rk,
                     const float* __restrict__ lnw, const float* __restrict__ lnb,
                     float* __restrict__ z) {
    const int t = blockIdx.x;
    const int tid = threadIdx.x;
    const int cbase = tid * 4;
    const size_t idx = (size_t)t * C + cbase;
    float4 yv = *(const float4*)(y + idx);
    float s1 = yv.x + yv.y + yv.z + yv.w;
    float s2 = yv.x * yv.x + yv.y * yv.y + yv.z * yv.z + yv.w * yv.w;
    float4 rv = *(const float4*)(r + idx);
    float4 kv = *(const float4*)(kadj + idx);
    float4 rkv = *(const float4*)(rk + cbase);
    float s3 = rv.x * kv.x * rkv.x + rv.y * kv.y * rkv.y +
               rv.z * kv.z * rkv.z + rv.w * kv.w * rkv.w;
#pragma unroll
    for (int off = 8; off > 0; off >>= 1) {
        s1 += __shfl_xor_sync(0xffffffffu, s1, off);
        s2 += __shfl_xor_sync(0xffffffffu, s2, off);
        s3 += __shfl_xor_sync(0xffffffffu, s3, off);
    }
    const float mu = s1 * (1.f / HS);
    const float var = s2 * (1.f / HS) - mu * mu;
    const float inv = rsqrtf(var + EPS_GN);
    float4 vv = *(const float4*)(v + idx);
    float4 gv = *(const float4*)(gg + idx);
    float4 lw = *(const float4*)(lnw + cbase);
    float4 lb = *(const float4*)(lnb + cbase);
    float4 res;
    res.x = (fmaf((yv.x - mu) * inv, lw.x, lb.x) + s3 * vv.x) * gv.x;
    res.y = (fmaf((yv.y - mu) * inv, lw.y, lb.y) + s3 * vv.y) * gv.y;
    res.z = (fmaf((yv.z - mu) * inv, lw.z, lb.z) + s3 * vv.z) * gv.z;
    res.w = (fmaf((yv.w - mu) * inv, lw.w, lb.w) + s3 * vv.w) * gv.w;
    *(float4*)(z + idx) = res;
}

// ---------------- launch ----------------
extern "C" void kernel_launch(void* const* d_in, const int* in_sizes, int n_in,
                              void* d_out, int out_size) {
    const float* x       = (const float*)d_in[0];
    const float* v_first = (const float*)d_in[1];
    const float* x_prev  = (const float*)d_in[2];
    const float* S0      = (const float*)d_in[3];
    const float* m_r = (const float*)d_in[4];
    const float* m_w = (const float*)d_in[5];
    const float* m_k = (const float*)d_in[6];
    const float* m_v = (const float*)d_in[7];
    const float* m_a = (const float*)d_in[8];
    const float* m_g = (const float*)d_in[9];

    const float *w0, *w1, *w2, *a0, *a1, *a2, *v0, *v1, *v2, *g1, *g2, *k_k, *k_a, *r_k;
    if (in_sizes[11] == C) {
        w0 = (const float*)d_in[10]; a0 = (const float*)d_in[11];
        v0 = (const float*)d_in[12]; k_k = (const float*)d_in[13];
        k_a = (const float*)d_in[14];
        w1 = (const float*)d_in[15]; w2 = (const float*)d_in[16];
        a1 = (const float*)d_in[17]; a2 = (const float*)d_in[18];
        v1 = (const float*)d_in[19]; v2 = (const float*)d_in[20];
        g1 = (const float*)d_in[21]; g2 = (const float*)d_in[22];
        r_k = (const float*)d_in[23];
    } else {
        w0 = (const float*)d_in[10]; w1 = (const float*)d_in[11];
        w2 = (const float*)d_in[12];
        a0 = (const float*)d_in[13]; a1 = (const float*)d_in[14];
        a2 = (const float*)d_in[15];
        v0 = (const float*)d_in[16]; v1 = (const float*)d_in[17];
        v2 = (const float*)d_in[18];
        g1 = (const float*)d_in[19]; g2 = (const float*)d_in[20];
        k_k = (const float*)d_in[21]; k_a = (const float*)d_in[22];
        r_k = (const float*)d_in[23];
    }

    const float* Wr = (const float*)d_in[24];
    const float* Wk = (const float*)d_in[25];
    const float* Wv = (const float*)d_in[26];
    const float* Wo = (const float*)d_in[27];
    const float* lnw = (const float*)d_in[28];
    const float* lnb = (const float*)d_in[29];
    const int*   cu  = (const int*)d_in[30];
    const int ncu = in_sizes[30];
    float* out = (float*)d_out;

    float* s = nullptr;
    cudaGetSymbolAddress((void**)&s, g_scratch);
    const size_t P = (size_t)T * C;
    float* xr = s;          float* xw = s + P;      float* xk = s + 2 * P;
    float* xv = s + 3 * P;  float* xa = s + 4 * P;  float* xg = s + 5 * P;
    float* rb = s + 6 * P;  float* kb = s + 7 * P;  float* vbuf = s + 8 * P;
    float* ewb = s + 9 * P; float* ab = s + 10 * P; float* gbuf = s + 11 * P;
    float* aab = s + 12 * P; float* bbb = s + 13 * P; float* kadj = s + 14 * P;
    float* yb = s + 15 * P;  float* zb = s + 16 * P;
    float* hw = s + 17 * P;
    float* ha = hw + (size_t)T * 64;
    float* hv = ha + (size_t)T * 64;
    float* hg = hv + (size_t)T * 32;

    const int GEMM_SMEM = 2 * 4 * STAGE_U32 * 4;
    static int smem_set = 0;
    if (!smem_set) {
        cudaFuncSetAttribute(k_gemm_mma, cudaFuncAttributeMaxDynamicSharedMemorySize,
                             GEMM_SMEM);
        smem_set = 1;
    }

    k_shift_mix<<<T, 256>>>(x, x_prev, cu, ncu, m_r, m_w, m_k, m_v, m_a, m_g,
                            xr, xw, xk, xv, xa, xg);

    dim3 gemm_grid(C / 128, T / 128);
    k_gemm_mma<<<gemm_grid, 256, GEMM_SMEM>>>(xr, Wr, rb);
    k_gemm_mma<<<gemm_grid, 256, GEMM_SMEM>>>(xk, Wk, kb);
    k_gemm_mma<<<gemm_grid, 256, GEMM_SMEM>>>(xv, Wv, vbuf);

    k_stage1<64, 1><<<T / 32, 256>>>(xw, w1, hw);
    k_stage1<64, 0><<<T / 32, 256>>>(xa, a1, ha);
    k_stage1<32, 0><<<T / 32, 256>>>(xv, v1, hv);
    k_stage1<128, 2><<<T / 32, 256>>>(xg, g1, hg);

    dim3 s2grid(C / 128, T / 16);
    k_stage2<64, 0><<<s2grid, 128>>>(hw, w2, w0, nullptr, nullptr, ewb);
    k_stage2<64, 1><<<s2grid, 128>>>(ha, a2, a0, nullptr, nullptr, ab);
    k_stage2<32, 2><<<s2grid, 128>>>(hv, v2, v0, vbuf, v_first, vbuf);
    k_stage2<128, 3><<<s2grid, 128>>>(hg, g2, nullptr, nullptr, nullptr, gbuf);

    k_prep<<<T, 256>>>(kb, ab, k_k, k_a, aab, bbb, kadj);

    k_scan<<<dim3(NH, 16), 32>>>(rb, ewb, aab, bbb, kadj, vbuf, S0, yb);

    k_gn<<<T, 256>>>(yb, rb, kadj, vbuf, gbuf, r_k, lnw, lnb, zb);

    k_gemm_mma<<<gemm_grid, 256, GEMM_SMEM>>>(zb, Wo, out);
}

// round 14
// speedup vs baseline: 1.0847x; 1.0771x over previous
#include <cuda_runtime.h>
#include <math.h>

static const int T  = 2048;
static const int C  = 1024;
static const int NH = 16;
static const int HS = 64;
#define EPS_GN 0.00064f

typedef unsigned long long u64;
typedef unsigned int u32;

// ---------------- f32x2 packed helpers ----------------
__device__ __forceinline__ u64 fma2(u64 a, u64 b, u64 c) {
    u64 d; asm("fma.rn.f32x2 %0, %1, %2, %3;" : "=l"(d) : "l"(a), "l"(b), "l"(c)); return d;
}
__device__ __forceinline__ u64 mul2(u64 a, u64 b) {
    u64 d; asm("mul.rn.f32x2 %0, %1, %2;" : "=l"(d) : "l"(a), "l"(b)); return d;
}
__device__ __forceinline__ u64 add2(u64 a, u64 b) {
    u64 d; asm("add.rn.f32x2 %0, %1, %2;" : "=l"(d) : "l"(a), "l"(b)); return d;
}
__device__ __forceinline__ u64 pack2(float lo, float hi) {
    u64 d; asm("mov.b64 %0, {%1, %2};" : "=l"(d) : "f"(lo), "f"(hi)); return d;
}
__device__ __forceinline__ float2 unpack2(u64 v) {
    float2 r; asm("mov.b64 {%0, %1}, %2;" : "=f"(r.x), "=f"(r.y) : "l"(v)); return r;
}
__device__ __forceinline__ void cp16(unsigned s, const float* g) {
    asm volatile("cp.async.ca.shared.global [%0], [%1], 16;" :: "r"(s), "l"(g));
}

// ---------------- scratch ----------------
__device__ float g_scratch[(size_t)17 * 2048 * 1024 + (size_t)2048 * 288];

// ---------------- K1: token shift + 6-way mix ----------------
__global__ void k_shift_mix(const float* __restrict__ x, const float* __restrict__ x_prev,
                            const int* __restrict__ cu, int ncu,
                            const float* __restrict__ mr, const float* __restrict__ mw,
                            const float* __restrict__ mk, const float* __restrict__ mv,
                            const float* __restrict__ ma, const float* __restrict__ mg,
                            float* __restrict__ oxr, float* __restrict__ oxw,
                            float* __restrict__ oxk, float* __restrict__ oxv,
                            float* __restrict__ oxa, float* __restrict__ oxg) {
    const int t = blockIdx.x;
    int kind = (t == 0) ? 1 : 0;
    int prow = 0;
    for (int i = 0; i + 1 < ncu; i++) if (cu[i] == t) { kind = 2; prow = i; }
    const int c = threadIdx.x * 4;
    const size_t off = (size_t)t * C + c;
    float4 xc = *(const float4*)(x + off);
    float4 pv;
    if (kind == 0)      pv = *(const float4*)(x + off - C);
    else if (kind == 2) pv = *(const float4*)(x_prev + (size_t)prow * C + c);
    else                pv = make_float4(0.f, 0.f, 0.f, 0.f);
    float4 dx = make_float4(pv.x - xc.x, pv.y - xc.y, pv.z - xc.z, pv.w - xc.w);
#define MIXOUT(dst, m) { \
    float4 mm = *(const float4*)((m) + c); \
    float4 r_ = make_float4(fmaf(dx.x, mm.x, xc.x), fmaf(dx.y, mm.y, xc.y), \
                            fmaf(dx.z, mm.z, xc.z), fmaf(dx.w, mm.w, xc.w)); \
    *(float4*)((dst) + off) = r_; }
    MIXOUT(oxr, mr) MIXOUT(oxw, mw) MIXOUT(oxk, mk)
    MIXOUT(oxv, mv) MIXOUT(oxa, ma) MIXOUT(oxg, mg)
#undef MIXOUT
}

// ---------------- K2: bf16x3 mma.sync NT GEMM, double-buffered, SROW=20 ---------------
#define SROW 20
#define STAGE_U32 (128 * SROW)

#define MMA_BF16(ac, av, bv) \
    asm volatile("mma.sync.aligned.m16n8k16.row.col.f32.bf16.bf16.f32 " \
        "{%0,%1,%2,%3},{%4,%5,%6,%7},{%8,%9},{%0,%1,%2,%3};" \
        : "+f"((ac)[0]), "+f"((ac)[1]), "+f"((ac)[2]), "+f"((ac)[3]) \
        : "r"((av)[0]), "r"((av)[1]), "r"((av)[2]), "r"((av)[3]), \
          "r"((bv)[0]), "r"((bv)[1]))

__global__ void __launch_bounds__(256) k_gemm_mma(const float* __restrict__ A,
                                                  const float* __restrict__ B,
                                                  float* __restrict__ Cg) {
    extern __shared__ u32 smem_dyn[];
    const int bm = blockIdx.y * 128;
    const int bn = blockIdx.x * 128;
    const int tid = threadIdx.x;
    const int wid = tid >> 5;
    const int lane = tid & 31;
    const int wm = (wid & 1) * 64;
    const int wn = (wid >> 1) * 32;
    const int g = lane >> 2;
    const int tg = lane & 3;

    float acc[4][4][4];
#pragma unroll
    for (int mt = 0; mt < 4; mt++)
#pragma unroll
        for (int nt = 0; nt < 4; nt++)
#pragma unroll
            for (int q = 0; q < 4; q++) acc[mt][nt][q] = 0.f;

    float2 aPre[8], bPre[8];
#define LDG_CHUNK(cc) { \
    _Pragma("unroll") \
    for (int i = 0; i < 8; i++) { \
        const int p = i * 256 + tid; \
        const int row = p >> 4; \
        const int kk = (p & 15) * 2; \
        aPre[i] = *(const float2*)(A + (size_t)(bm + row) * C + (cc) * 32 + kk); \
        bPre[i] = *(const float2*)(B + (size_t)(bn + row) * C + (cc) * 32 + kk); \
    } }

#define SPLIT_STORE(f2, Hbuf, Lbuf, w) { \
    u32 bx_ = __float_as_uint((f2).x), by_ = __float_as_uint((f2).y); \
    u32 hx_ = bx_ & 0xFFFF0000u, hy_ = by_ & 0xFFFF0000u; \
    (Hbuf)[w] = (hx_ >> 16) | hy_; \
    float lx_ = (f2).x - __uint_as_float(hx_); \
    float ly_ = (f2).y - __uint_as_float(hy_); \
    u32 lp_; \
    asm("cvt.rn.satfinite.bf16x2.f32 %0, %1, %2;" : "=r"(lp_) : "f"(ly_), "f"(lx_)); \
    (Lbuf)[w] = lp_; }

#define STS_CHUNK(st) { \
    u32* Ah_ = smem_dyn + (st) * 4 * STAGE_U32; \
    u32* Al_ = Ah_ + STAGE_U32; \
    u32* Bh_ = Al_ + STAGE_U32; \
    u32* Bl_ = Bh_ + STAGE_U32; \
    _Pragma("unroll") \
    for (int i = 0; i < 8; i++) { \
        const int p = i * 256 + tid; \
        const int row = p >> 4; \
        const int colw = p & 15; \
        const u32 w_ = (u32)(row * SROW + colw); \
        SPLIT_STORE(aPre[i], Ah_, Al_, w_) \
        SPLIT_STORE(bPre[i], Bh_, Bl_, w_) \
    } }

    LDG_CHUNK(0)
    STS_CHUNK(0)
    __syncthreads();
    LDG_CHUNK(1)

    const int NCHUNK = C / 32;
    for (int c = 0; c < NCHUNK; c++) {
        const u32* Ah = smem_dyn + (c & 1) * 4 * STAGE_U32;
        const u32* Al = Ah + STAGE_U32;
        const u32* Bh = Al + STAGE_U32;
        const u32* Bl = Bh + STAGE_U32;

        if (c + 1 < NCHUNK) {
            STS_CHUNK((c + 1) & 1)
        }
        if (c + 2 < NCHUNK) LDG_CHUNK(c + 2)

#pragma unroll
        for (int k16 = 0; k16 < 2; k16++) {
            const int colb = k16 * 8 + tg;

            u32 aH[4][4];
#pragma unroll
            for (int mt = 0; mt < 4; mt++) {
                const int base = (wm + mt * 16 + g) * SROW + colb;
                aH[mt][0] = Ah[base];
                aH[mt][1] = Ah[base + 8 * SROW];
                aH[mt][2] = Ah[base + 4];
                aH[mt][3] = Ah[base + 8 * SROW + 4];
            }
            u32 bH[4][2];
#pragma unroll
            for (int nt = 0; nt < 4; nt++) {
                const int base = (wn + nt * 8 + g) * SROW + colb;
                bH[nt][0] = Bh[base];
                bH[nt][1] = Bh[base + 4];
            }
#pragma unroll
            for (int mt = 0; mt < 4; mt++)
#pragma unroll
                for (int nt = 0; nt < 4; nt++)
                    MMA_BF16(acc[mt][nt], aH[mt], bH[nt]);

            u32 bL[4][2];
#pragma unroll
            for (int nt = 0; nt < 4; nt++) {
                const int base = (wn + nt * 8 + g) * SROW + colb;
                bL[nt][0] = Bl[base];
                bL[nt][1] = Bl[base + 4];
            }
#pragma unroll
            for (int mt = 0; mt < 4; mt++)
#pragma unroll
                for (int nt = 0; nt < 4; nt++)
                    MMA_BF16(acc[mt][nt], aH[mt], bL[nt]);

            u32 aL[4][4];
#pragma unroll
            for (int mt = 0; mt < 4; mt++) {
                const int base = (wm + mt * 16 + g) * SROW + colb;
                aL[mt][0] = Al[base];
                aL[mt][1] = Al[base + 8 * SROW];
                aL[mt][2] = Al[base + 4];
                aL[mt][3] = Al[base + 8 * SROW + 4];
            }
#pragma unroll
            for (int mt = 0; mt < 4; mt++)
#pragma unroll
                for (int nt = 0; nt < 4; nt++)
                    MMA_BF16(acc[mt][nt], aL[mt], bH[nt]);
        }
        __syncthreads();
    }

#pragma unroll
    for (int mt = 0; mt < 4; mt++) {
#pragma unroll
        for (int nt = 0; nt < 4; nt++) {
            const int row = bm + wm + mt * 16 + g;
            const int col = bn + wn + nt * 8 + tg * 2;
            *(float2*)(Cg + (size_t)row * C + col) =
                make_float2(acc[mt][nt][0], acc[mt][nt][1]);
            *(float2*)(Cg + (size_t)(row + 8) * C + col) =
                make_float2(acc[mt][nt][2], acc[mt][nt][3]);
        }
    }
#undef LDG_CHUNK
#undef STS_CHUNK
#undef SPLIT_STORE
}

// ---------------- K3: stage-1 LoRA GEMM (register tiled) ----------------
// out[t][j] = act(X[t,:] @ W[:,j]). 16-row blocks, thread tile 2t x (KO/32).
template <int KO, int ACT>
__global__ void __launch_bounds__(256) k_stage1(const float* __restrict__ X,
                                                const float* __restrict__ W,
                                                float* __restrict__ out) {
    const int CW = KO / 32;             // cols per thread (1, 2 or 4)
    __shared__ float Xs[16][33];
    __shared__ float Ws[32][KO + 8];
    const int t0 = blockIdx.x * 16;
    const int tid = threadIdx.x;
    const int rg = tid >> 5;            // 0..7 -> rows rg*2 + {0,1}
    const int cg = tid & 31;            // 0..31 -> cols cg*CW
    const int jb = cg * CW;

    float acc[2][CW];
#pragma unroll
    for (int r = 0; r < 2; r++)
#pragma unroll
        for (int w = 0; w < CW; w++) acc[r][w] = 0.f;

    for (int cb = 0; cb < C; cb += 32) {
#pragma unroll
        for (int i = 0; i < 2; i++) {
            const int p = i * 256 + tid;
            Xs[p >> 5][p & 31] = X[(size_t)(t0 + (p >> 5)) * C + cb + (p & 31)];
        }
#pragma unroll
        for (int i = 0; i < KO / 8; i++) {
            const int p = i * 256 + tid;
            const int r = p / KO;
            const int j = p - r * KO;
            Ws[r][j] = W[(size_t)(cb + r) * KO + j];
        }
        __syncthreads();
#pragma unroll
        for (int cc = 0; cc < 32; cc++) {
            const float x0 = Xs[rg * 2][cc];
            const float x1 = Xs[rg * 2 + 1][cc];
            float wv[CW];
            if (CW == 1) {
                wv[0] = Ws[cc][jb];
            } else if (CW == 2) {
                float2 t2 = *(const float2*)&Ws[cc][jb];
                wv[0] = t2.x; wv[1] = t2.y;
            } else {
                float4 t4 = *(const float4*)&Ws[cc][jb];
                wv[0] = t4.x; wv[1] = t4.y; wv[2] = t4.z; wv[3] = t4.w;
            }
#pragma unroll
            for (int w = 0; w < CW; w++) {
                acc[0][w] = fmaf(x0, wv[w], acc[0][w]);
                acc[1][w] = fmaf(x1, wv[w], acc[1][w]);
            }
        }
        __syncthreads();
    }
#pragma unroll
    for (int r = 0; r < 2; r++) {
#pragma unroll
        for (int w = 0; w < CW; w++) {
            float val = acc[r][w];
            if (ACT == 1) val = tanhf(val);
            else if (ACT == 2) val = 1.f / (1.f + expf(-val));
            out[(size_t)(t0 + rg * 2 + r) * KO + jb + w] = val;
        }
    }
}

// ---------------- K4: stage-2 LoRA GEMM + fused epilogue (register tiled) -------------
// 32t x 128o blocks, thread tile 2t x 8o.
template <int KI, int EPI>
__global__ void __launch_bounds__(256) k_stage2(const float* __restrict__ Hh,
                                                const float* __restrict__ W2,
                                                const float* __restrict__ bias,
                                                const float* __restrict__ e1,
                                                const float* __restrict__ e2,
                                                float* __restrict__ out) {
    __shared__ float Hs[32][KI + 1];
    __shared__ float W2s[32][132];
    const int tb = blockIdx.y * 32;
    const int o0 = blockIdx.x * 128;
    const int tid = threadIdx.x;
    const int rg = tid >> 4;            // 0..15 -> rows rg*2 + {0,1}
    const int cg = tid & 15;            // 0..15 -> cols cg*8
    const int ob = cg * 8;

    // load H tile once
#pragma unroll
    for (int i = 0; i < KI / 8; i++) {
        const int p = i * 256 + tid;
        const int r = p / KI;
        const int j = p - r * KI;
        Hs[r][j] = Hh[(size_t)(tb + r) * KI + j];
    }

    float acc[2][8];
#pragma unroll
    for (int r = 0; r < 2; r++)
#pragma unroll
        for (int w = 0; w < 8; w++) acc[r][w] = 0.f;

    for (int cb = 0; cb < KI; cb += 32) {
        __syncthreads();
#pragma unroll
        for (int i = 0; i < 16; i++) {
            const int p = i * 256 + tid;
            W2s[p >> 7][p & 127] = W2[(size_t)(cb + (p >> 7)) * C + o0 + (p & 127)];
        }
        __syncthreads();
#pragma unroll
        for (int cc = 0; cc < 32; cc++) {
            const float h0 = Hs[rg * 2][cb + cc];
            const float h1 = Hs[rg * 2 + 1][cb + cc];
            float4 w0 = *(const float4*)&W2s[cc][ob];
            float4 w1 = *(const float4*)&W2s[cc][ob + 4];
            acc[0][0] = fmaf(h0, w0.x, acc[0][0]); acc[1][0] = fmaf(h1, w0.x, acc[1][0]);
            acc[0][1] = fmaf(h0, w0.y, acc[0][1]); acc[1][1] = fmaf(h1, w0.y, acc[1][1]);
            acc[0][2] = fmaf(h0, w0.z, acc[0][2]); acc[1][2] = fmaf(h1, w0.z, acc[1][2]);
            acc[0][3] = fmaf(h0, w0.w, acc[0][3]); acc[1][3] = fmaf(h1, w0.w, acc[1][3]);
            acc[0][4] = fmaf(h0, w1.x, acc[0][4]); acc[1][4] = fmaf(h1, w1.x, acc[1][4]);
            acc[0][5] = fmaf(h0, w1.y, acc[0][5]); acc[1][5] = fmaf(h1, w1.y, acc[1][5]);
            acc[0][6] = fmaf(h0, w1.z, acc[0][6]); acc[1][6] = fmaf(h1, w1.z, acc[1][6]);
            acc[0][7] = fmaf(h0, w1.w, acc[0][7]); acc[1][7] = fmaf(h1, w1.w, acc[1][7]);
        }
    }

    float bv[8];
    if (EPI != 3) {
#pragma unroll
        for (int w = 0; w < 8; w++) bv[w] = bias[o0 + ob + w];
    } else {
#pragma unroll
        for (int w = 0; w < 8; w++) bv[w] = 0.f;
    }

#pragma unroll
    for (int r = 0; r < 2; r++) {
        const size_t idx = (size_t)(tb + rg * 2 + r) * C + o0 + ob;
        float res[8];
#pragma unroll
        for (int w = 0; w < 8; w++) {
            float zv = acc[r][w] + bv[w];
            if (EPI == 0) {
                float xn = -zv;
                float sp = (xn > 20.f) ? xn : log1pf(expf(xn));
                res[w] = expf(-expf(-sp - 0.5f));
            } else if (EPI == 1) {
                res[w] = 1.f / (1.f + expf(-zv));
            } else if (EPI == 3) {
                res[w] = zv;
            } else {
                res[w] = zv;   // EPI==2 handled below
            }
        }
        if (EPI == 2) {
            float4 vr0 = *(const float4*)(e1 + idx);
            float4 vr1 = *(const float4*)(e1 + idx + 4);
            float4 vf0 = *(const float4*)(e2 + idx);
            float4 vf1 = *(const float4*)(e2 + idx + 4);
            float vre[8] = {vr0.x, vr0.y, vr0.z, vr0.w, vr1.x, vr1.y, vr1.z, vr1.w};
            float vfe[8] = {vf0.x, vf0.y, vf0.z, vf0.w, vf1.x, vf1.y, vf1.z, vf1.w};
#pragma unroll
            for (int w = 0; w < 8; w++) {
                float sg = 1.f / (1.f + expf(-res[w]));
                res[w] = fmaf(vfe[w] - vre[w], sg, vre[w]);
            }
        }
        *(float4*)(out + idx)     = make_float4(res[0], res[1], res[2], res[3]);
        *(float4*)(out + idx + 4) = make_float4(res[4], res[5], res[6], res[7]);
    }
}

// ---------------- K5: scan-input prep ----------------
__global__ void k_prep(const float* __restrict__ kin, const float* __restrict__ ain,
                       const float* __restrict__ kkw, const float* __restrict__ kaw,
                       float* __restrict__ aab, float* __restrict__ bbb,
                       float* __restrict__ kadj) {
    const int t = blockIdx.x;
    const int tid = threadIdx.x;
    const int cbase = tid * 4;
    const size_t idx = (size_t)t * C + cbase;
    float4 kv = *(const float4*)(kin + idx);
    float4 av = *(const float4*)(ain + idx);
    float4 kw = *(const float4*)(kkw + cbase);
    float4 aw = *(const float4*)(kaw + cbase);
    float4 kk = make_float4(kv.x * kw.x, kv.y * kw.y, kv.z * kw.z, kv.w * kw.w);
    float ss = kk.x * kk.x + kk.y * kk.y + kk.z * kk.z + kk.w * kk.w;
#pragma unroll
    for (int off = 8; off > 0; off >>= 1)
        ss += __shfl_xor_sync(0xffffffffu, ss, off);
    float inv = 1.f / fmaxf(sqrtf(ss), 1e-12f);
    float4 kn = make_float4(kk.x * inv, kk.y * inv, kk.z * inv, kk.w * inv);
    *(float4*)(aab + idx) = make_float4(-kn.x, -kn.y, -kn.z, -kn.w);
    *(float4*)(bbb + idx) = make_float4(kn.x * av.x, kn.y * av.y, kn.z * av.z, kn.w * av.w);
    *(float4*)(kadj + idx) = make_float4(
        kv.x * fmaf(av.x - 1.f, aw.x, 1.f),
        kv.y * fmaf(av.y - 1.f, aw.y, 1.f),
        kv.z * fmaf(av.z - 1.f, aw.z, 1.f),
        kv.w * fmaf(av.w - 1.f, aw.w, 1.f));
}

// ---------------- K6: RWKV-7 scan — 4 v-rows/block, parallel 7-shfl reductions --------
union U8 { float f[8]; u64 u[4]; float4 v[2]; };

#define RING_SLOTS 16
#define CHUNK 8

__global__ void __launch_bounds__(32) k_scan(const float* __restrict__ rb,
                                             const float* __restrict__ ewb,
                                             const float* __restrict__ aab,
                                             const float* __restrict__ bbb,
                                             const float* __restrict__ kb,
                                             const float* __restrict__ vb,
                                             const float* __restrict__ S0,
                                             float* __restrict__ y) {
    __shared__ float ring[RING_SLOTS][6 * HS];
    const int h  = blockIdx.x;
    const int vg = blockIdx.y;
    const int tid = threadIdx.x;
    const int jg = tid & 7;
    const int vr = tid >> 3;
    const int vrow = vg * 4 + vr;
    const int jb = jg * 8;

    U8 S;
    S.v[0] = *(const float4*)(S0 + (size_t)h * HS * HS + (size_t)vrow * HS + jb);
    S.v[1] = *(const float4*)(S0 + (size_t)h * HS * HS + (size_t)vrow * HS + jb + 4);

    const int off16 = (tid & 15) << 2;
    const int arr0 = tid >> 4;
    const int arr1 = arr0 + 2;
    const int arr2 = arr0 + 4;
    const float* s0 = (arr0 == 0 ? rb  : ewb) + (size_t)h * HS + off16;
    const float* s1 = (arr1 == 2 ? aab : bbb) + (size_t)h * HS + off16;
    const float* s2 = (arr2 == 4 ? kb  : vb ) + (size_t)h * HS + off16;
    unsigned base_u = (unsigned)__cvta_generic_to_shared(&ring[0][0]);
    const unsigned d0 = base_u + (unsigned)(arr0 * HS + off16) * 4u;
    const unsigned d1 = base_u + (unsigned)(arr1 * HS + off16) * 4u;
    const unsigned d2 = base_u + (unsigned)(arr2 * HS + off16) * 4u;

#define ISSUE_CHUNK(cb) { \
    _Pragma("unroll") \
    for (int s_ = 0; s_ < CHUNK; s_++) { \
        int st_ = (cb) * CHUNK + s_; \
        int slot_ = st_ & (RING_SLOTS - 1); \
        if (st_ >= T) st_ = T - 1; \
        size_t so_ = (size_t)st_ * C; \
        unsigned sb_ = (unsigned)slot_ * (6 * HS * 4); \
        cp16(d0 + sb_, s0 + so_); \
        cp16(d1 + sb_, s1 + so_); \
        cp16(d2 + sb_, s2 + so_); \
    } \
    asm volatile("cp.async.commit_group;"); }

    ISSUE_CHUNK(0)
    ISSUE_CHUNK(1)

    float oprev = 0.f;
    const size_t ybase = (size_t)h * HS + vrow;
    const int NCH = T / CHUNK;

    for (int c = 0; c < NCH; c++) {
        asm volatile("cp.async.wait_group 1;");
        __syncwarp();

#pragma unroll
        for (int s = 0; s < CHUNK; s++) {
            const int t = c * CHUNK + s;
            if (t > 0 && jg == 0)
                y[(size_t)(t - 1) * C + ybase] = oprev;

            const float* sp = &ring[t & (RING_SLOTS - 1)][0];
            U8 Rv, Ev, Av, Bv, Kv;
            Rv.v[0] = *(const float4*)&sp[0 * HS + jb];
            Rv.v[1] = *(const float4*)&sp[0 * HS + jb + 4];
            Ev.v[0] = *(const float4*)&sp[1 * HS + jb];
            Ev.v[1] = *(const float4*)&sp[1 * HS + jb + 4];
            Av.v[0] = *(const float4*)&sp[2 * HS + jb];
            Av.v[1] = *(const float4*)&sp[2 * HS + jb + 4];
            Bv.v[0] = *(const float4*)&sp[3 * HS + jb];
            Bv.v[1] = *(const float4*)&sp[3 * HS + jb + 4];
            Kv.v[0] = *(const float4*)&sp[4 * HS + jb];
            Kv.v[1] = *(const float4*)&sp[4 * HS + jb + 4];
            const float vt = sp[5 * HS + vrow];

            u64 sacc0 = mul2(S.u[0], Av.u[0]);
            u64 sacc1 = mul2(S.u[1], Av.u[1]);
            sacc0 = fma2(S.u[2], Av.u[2], sacc0);
            sacc1 = fma2(S.u[3], Av.u[3], sacc1);
            float2 sp2 = unpack2(add2(sacc0, sacc1));
            float sal = sp2.x + sp2.y;
            float x1 = __shfl_xor_sync(0xffffffffu, sal, 1);
            float x2 = __shfl_xor_sync(0xffffffffu, sal, 2);
            float x3 = __shfl_xor_sync(0xffffffffu, sal, 3);
            float x4 = __shfl_xor_sync(0xffffffffu, sal, 4);
            float x5 = __shfl_xor_sync(0xffffffffu, sal, 5);
            float x6 = __shfl_xor_sync(0xffffffffu, sal, 6);
            float x7 = __shfl_xor_sync(0xffffffffu, sal, 7);

            u64 vt2 = pack2(vt, vt);
            u64 pre[4];
#pragma unroll
            for (int q = 0; q < 4; q++)
                pre[q] = fma2(S.u[q], Ev.u[q], mul2(vt2, Kv.u[q]));

            float sa = ((sal + x1) + (x2 + x3)) + ((x4 + x5) + (x6 + x7));
            u64 sa2 = pack2(sa, sa);

            u64 oa0 = 0ull, oa1 = 0ull;
#pragma unroll
            for (int q = 0; q < 4; q += 2) {
                S.u[q]     = fma2(sa2, Bv.u[q],     pre[q]);
                S.u[q + 1] = fma2(sa2, Bv.u[q + 1], pre[q + 1]);
                oa0 = fma2(S.u[q],     Rv.u[q],     oa0);
                oa1 = fma2(S.u[q + 1], Rv.u[q + 1], oa1);
            }
            float2 op2 = unpack2(add2(oa0, oa1));
            float ol = op2.x + op2.y;
            float y1 = __shfl_xor_sync(0xffffffffu, ol, 1);
            float y2 = __shfl_xor_sync(0xffffffffu, ol, 2);
            float y3 = __shfl_xor_sync(0xffffffffu, ol, 3);
            float y4 = __shfl_xor_sync(0xffffffffu, ol, 4);
            float y5 = __shfl_xor_sync(0xffffffffu, ol, 5);
            float y6 = __shfl_xor_sync(0xffffffffu, ol, 6);
            float y7 = __shfl_xor_sync(0xffffffffu, ol, 7);
            oprev = ((ol + y1) + (y2 + y3)) + ((y4 + y5) + (y6 + y7));
        }

        ISSUE_CHUNK(c + 2)
    }
    if (jg == 0)
        y[(size_t)(T - 1) * C + ybase] = oprev;
#undef ISSUE_CHUNK
}

// ---------------- K7: GroupNorm + bonus + gate ----------------
__global__ void k_gn(const float* __restrict__ y, const float* __restrict__ r,
                     const float* __restrict__ kadj, const float* __restrict__ v,
                     const float* __restrict__ gg, const float* __restrict__ rk,
                     const float* __restrict__ lnw, const float* __restrict__ lnb,
                     float* __restrict__ z) {
    const int t = blockIdx.x;
    const int tid = threadIdx.x;
    const int cbase = tid * 4;
    const size_t idx = (size_t)t * C + cbase;
    float4 yv = *(const float4*)(y + idx);
    float s1 = yv.x + yv.y + yv.z + yv.w;
    float s2 = yv.x * yv.x + yv.y * yv.y + yv.z * yv.z + yv.w * yv.w;
    float4 rv = *(const float4*)(r + idx);
    float4 kv = *(const float4*)(kadj + idx);
    float4 rkv = *(const float4*)(rk + cbase);
    float s3 = rv.x * kv.x * rkv.x + rv.y * kv.y * rkv.y +
               rv.z * kv.z * rkv.z + rv.w * kv.w * rkv.w;
#pragma unroll
    for (int off = 8; off > 0; off >>= 1) {
        s1 += __shfl_xor_sync(0xffffffffu, s1, off);
        s2 += __shfl_xor_sync(0xffffffffu, s2, off);
        s3 += __shfl_xor_sync(0xffffffffu, s3, off);
    }
    const float mu = s1 * (1.f / HS);
    const float var = s2 * (1.f / HS) - mu * mu;
    const float inv = rsqrtf(var + EPS_GN);
    float4 vv = *(const float4*)(v + idx);
    float4 gv = *(const float4*)(gg + idx);
    float4 lw = *(const float4*)(lnw + cbase);
    float4 lb = *(const float4*)(lnb + cbase);
    float4 res;
    res.x = (fmaf((yv.x - mu) * inv, lw.x, lb.x) + s3 * vv.x) * gv.x;
    res.y = (fmaf((yv.y - mu) * inv, lw.y, lb.y) + s3 * vv.y) * gv.y;
    res.z = (fmaf((yv.z - mu) * inv, lw.z, lb.z) + s3 * vv.z) * gv.z;
    res.w = (fmaf((yv.w - mu) * inv, lw.w, lb.w) + s3 * vv.w) * gv.w;
    *(float4*)(z + idx) = res;
}

// ---------------- launch ----------------
extern "C" void kernel_launch(void* const* d_in, const int* in_sizes, int n_in,
                              void* d_out, int out_size) {
    const float* x       = (const float*)d_in[0];
    const float* v_first = (const float*)d_in[1];
    const float* x_prev  = (const float*)d_in[2];
    const float* S0      = (const float*)d_in[3];
    const float* m_r = (const float*)d_in[4];
    const float* m_w = (const float*)d_in[5];
    const float* m_k = (const float*)d_in[6];
    const float* m_v = (const float*)d_in[7];
    const float* m_a = (const float*)d_in[8];
    const float* m_g = (const float*)d_in[9];

    const float *w0, *w1, *w2, *a0, *a1, *a2, *v0, *v1, *v2, *g1, *g2, *k_k, *k_a, *r_k;
    if (in_sizes[11] == C) {
        w0 = (const float*)d_in[10]; a0 = (const float*)d_in[11];
        v0 = (const float*)d_in[12]; k_k = (const float*)d_in[13];
        k_a = (const float*)d_in[14];
        w1 = (const float*)d_in[15]; w2 = (const float*)d_in[16];
        a1 = (const float*)d_in[17]; a2 = (const float*)d_in[18];
        v1 = (const float*)d_in[19]; v2 = (const float*)d_in[20];
        g1 = (const float*)d_in[21]; g2 = (const float*)d_in[22];
        r_k = (const float*)d_in[23];
    } else {
        w0 = (const float*)d_in[10]; w1 = (const float*)d_in[11];
        w2 = (const float*)d_in[12];
        a0 = (const float*)d_in[13]; a1 = (const float*)d_in[14];
        a2 = (const float*)d_in[15];
        v0 = (const float*)d_in[16]; v1 = (const float*)d_in[17];
        v2 = (const float*)d_in[18];
        g1 = (const float*)d_in[19]; g2 = (const float*)d_in[20];
        k_k = (const float*)d_in[21]; k_a = (const float*)d_in[22];
        r_k = (const float*)d_in[23];
    }

    const float* Wr = (const float*)d_in[24];
    const float* Wk = (const float*)d_in[25];
    const float* Wv = (const float*)d_in[26];
    const float* Wo = (const float*)d_in[27];
    const float* lnw = (const float*)d_in[28];
    const float* lnb = (const float*)d_in[29];
    const int*   cu  = (const int*)d_in[30];
    const int ncu = in_sizes[30];
    float* out = (float*)d_out;

    float* s = nullptr;
    cudaGetSymbolAddress((void**)&s, g_scratch);
    const size_t P = (size_t)T * C;
    float* xr = s;          float* xw = s + P;      float* xk = s + 2 * P;
    float* xv = s + 3 * P;  float* xa = s + 4 * P;  float* xg = s + 5 * P;
    float* rb = s + 6 * P;  float* kb = s + 7 * P;  float* vbuf = s + 8 * P;
    float* ewb = s + 9 * P; float* ab = s + 10 * P; float* gbuf = s + 11 * P;
    float* aab = s + 12 * P; float* bbb = s + 13 * P; float* kadj = s + 14 * P;
    float* yb = s + 15 * P;  float* zb = s + 16 * P;
    float* hw = s + 17 * P;
    float* ha = hw + (size_t)T * 64;
    float* hv = ha + (size_t)T * 64;
    float* hg = hv + (size_t)T * 32;

    const int GEMM_SMEM = 2 * 4 * STAGE_U32 * 4;
    static int smem_set = 0;
    if (!smem_set) {
        cudaFuncSetAttribute(k_gemm_mma, cudaFuncAttributeMaxDynamicSharedMemorySize,
                             GEMM_SMEM);
        smem_set = 1;
    }

    k_shift_mix<<<T, 256>>>(x, x_prev, cu, ncu, m_r, m_w, m_k, m_v, m_a, m_g,
                            xr, xw, xk, xv, xa, xg);

    dim3 gemm_grid(C / 128, T / 128);
    k_gemm_mma<<<gemm_grid, 256, GEMM_SMEM>>>(xr, Wr, rb);
    k_gemm_mma<<<gemm_grid, 256, GEMM_SMEM>>>(xk, Wk, kb);
    k_gemm_mma<<<gemm_grid, 256, GEMM_SMEM>>>(xv, Wv, vbuf);

    k_stage1<64, 1><<<T / 16, 256>>>(xw, w1, hw);
    k_stage1<64, 0><<<T / 16, 256>>>(xa, a1, ha);
    k_stage1<32, 0><<<T / 16, 256>>>(xv, v1, hv);
    k_stage1<128, 2><<<T / 16, 256>>>(xg, g1, hg);

    dim3 s2grid(C / 128, T / 32);
    k_stage2<64, 0><<<s2grid, 256>>>(hw, w2, w0, nullptr, nullptr, ewb);
    k_stage2<64, 1><<<s2grid, 256>>>(ha, a2, a0, nullptr, nullptr, ab);
    k_stage2<32, 2><<<s2grid, 256>>>(hv, v2, v0, vbuf, v_first, vbuf);
    k_stage2<128, 3><<<s2grid, 256>>>(hg, g2, nullptr, nullptr, nullptr, gbuf);

    k_prep<<<T, 256>>>(kb, ab, k_k, k_a, aab, bbb, kadj);

    k_scan<<<dim3(NH, 16), 32>>>(rb, ewb, aab, bbb, kadj, vbuf, S0, yb);

    k_gn<<<T, 256>>>(yb, rb, kadj, vbuf, gbuf, r_k, lnw, lnb, zb);

    k_gemm_mma<<<gemm_grid, 256, GEMM_SMEM>>>(zb, Wo, out);
}